// round 1
// baseline (speedup 1.0000x reference)
#include <cuda_runtime.h>
#include <math.h>

// Problem constants
#define BTOT   32768
#define TT     32
#define DD     2
#define HH     128
#define GG     512
#define PLL    12
#define OO     2

// Tiling
#define NB     32          // batch elements per CTA
#define NTH    256         // threads per CTA
#define WPITCH 129         // padded smem pitch for transposed weight chunk

// smem layout (floats)
#define OFF_H0    0        // 4096  h0 state   [NB][HH]
#define OFF_H1    4096     // 4096  h1 state   [NB][HH]
#define OFF_YS    8192     // 4096  ys (dropped layer0 out)
#define OFF_WT    12288    // 16512 transposed weight chunk [128][WPITCH]
#define OFF_B0    28800    // 512   combined bias layer0
#define OFF_B1    29312    // 512   combined bias layer1
#define OFF_BC    29824    // 512   combined bias decoder cell
#define OFF_WIH0  30336    // 1024  Wih0 (512x2)
#define OFF_WIHC  31360    // 1024  Wihc (512x2)
#define OFF_WOUT  32384    // 256   Wout (2x128)
#define OFF_BOUT  32640    // 4     bout
#define OFF_XS    32644    // 64    x_t   [NB][2]
#define OFF_INP   32708    // 64    decoder input [NB][2]
#define SMEM_FLOATS 32772
#define SMEM_BYTES  (SMEM_FLOATS * 4)

static __device__ __forceinline__ float sigm(float x) {
    return 1.0f / (1.0f + expf(-x));
}

// Stage a 128-row x 128-col fp32 weight chunk from global (row-major) into
// transposed smem WT[k][j] with pitch 129 (conflict-free reads & writes).
static __device__ __forceinline__ void stage_chunk(float* __restrict__ WT,
                                                   const float* __restrict__ src,
                                                   int tid)
{
#pragma unroll
    for (int i = 0; i < 64; ++i) {
        int idx = tid + i * NTH;         // 0..16383
        int j = idx >> 7;                // row (gate unit within chunk)
        int k = idx & 127;               // col (k index)
        WT[k * WPITCH + j] = src[idx];   // coalesced LDG, conflict-free STS
    }
}

// acc[m][n] += sum_k WT[k][tj+32m] * hb[(tb+8n)*HH + k]
static __device__ __forceinline__ void accum_panel(const float* __restrict__ WT,
                                                   const float* __restrict__ hb,
                                                   int tj, int tb,
                                                   float (&acc)[4][4])
{
#pragma unroll 4
    for (int k4 = 0; k4 < 32; ++k4) {
        float hv[4][4];
#pragma unroll
        for (int n = 0; n < 4; ++n) {
            float4 v = reinterpret_cast<const float4*>(hb + (tb + 8 * n) * HH)[k4];
            hv[n][0] = v.x; hv[n][1] = v.y; hv[n][2] = v.z; hv[n][3] = v.w;
        }
#pragma unroll
        for (int d = 0; d < 4; ++d) {
            float w[4];
#pragma unroll
            for (int m = 0; m < 4; ++m)
                w[m] = WT[(4 * k4 + d) * WPITCH + tj + 32 * m];
#pragma unroll
            for (int m = 0; m < 4; ++m)
#pragma unroll
                for (int n = 0; n < 4; ++n)
                    acc[m][n] = fmaf(w[m], hv[n][d], acc[m][n]);
        }
    }
}

__global__ void __launch_bounds__(NTH, 1)
mcdlstm_kernel(const float* __restrict__ obs,
               const float* __restrict__ Wih0, const float* __restrict__ Whh0,
               const float* __restrict__ bih0, const float* __restrict__ bhh0,
               const float* __restrict__ Wih1, const float* __restrict__ Whh1,
               const float* __restrict__ bih1, const float* __restrict__ bhh1,
               const float* __restrict__ Wihc, const float* __restrict__ Whhc,
               const float* __restrict__ bihc, const float* __restrict__ bhhc,
               const float* __restrict__ Wout, const float* __restrict__ bout,
               const float* __restrict__ enc_u, const float* __restrict__ hn_u,
               const float* __restrict__ dec_u,
               float* __restrict__ out)
{
    extern __shared__ float sm[];
    float* h0s   = sm + OFF_H0;
    float* h1s   = sm + OFF_H1;
    float* yss   = sm + OFF_YS;
    float* WT    = sm + OFF_WT;
    float* b0s   = sm + OFF_B0;
    float* b1s   = sm + OFF_B1;
    float* bcs   = sm + OFF_BC;
    float* wih0s = sm + OFF_WIH0;
    float* wihcs = sm + OFF_WIHC;
    float* wouts = sm + OFF_WOUT;
    float* bouts = sm + OFF_BOUT;
    float* xs    = sm + OFF_XS;
    float* inp   = sm + OFF_INP;

    const int tid = threadIdx.x;
    const int tj  = tid & 31;   // gate-unit lane: j = tj + 32*m
    const int tb  = tid >> 5;   // batch lane:     b = tb + 8*n
    const int bbase = blockIdx.x * NB;
    const float DSC = (float)(1.0 / 0.7);   // dropout scale 1/(1-P)

    // --- init ---
    for (int i = tid; i < 8192; i += NTH) sm[i] = 0.0f;   // h0s, h1s
    for (int i = tid; i < GG; i += NTH) {
        b0s[i] = bih0[i] + bhh0[i];
        b1s[i] = bih1[i] + bhh1[i];
        bcs[i] = bihc[i] + bhhc[i];
    }
    for (int i = tid; i < GG * 2; i += NTH) {
        wih0s[i] = Wih0[i];
        wihcs[i] = Wihc[i];
    }
    if (tid < OO * HH) wouts[tid] = Wout[tid];
    if (tid < OO)      bouts[tid] = bout[tid];

    float c0r[4][4], c1r[4][4], t1r[4][4];
#pragma unroll
    for (int m = 0; m < 4; ++m)
#pragma unroll
        for (int n = 0; n < 4; ++n) { c0r[m][n] = 0.0f; c1r[m][n] = 0.0f; t1r[m][n] = 0.0f; }

    // ======================= encoder: 32 time steps =======================
    for (int t = 0; t < TT; ++t) {
        if (tid < NB * DD) {
            int b = tid >> 1, d = tid & 1;
            xs[tid] = obs[((size_t)(bbase + b) * TT + t) * DD + d];
        }
        // ---------------- layer 0 (input x_t, state h0/c0) ----------------
        for (int qq = 0; qq < 4; ++qq) {
            int q = ((qq & 1) << 1) | (qq >> 1);   // pass order: i(0), g(2), f(1), o(3)
            __syncthreads();
            stage_chunk(WT, Whh0 + (size_t)q * 128 * HH, tid);
            __syncthreads();
            float acc[4][4];
#pragma unroll
            for (int m = 0; m < 4; ++m) {
                int row = q * 128 + tj + 32 * m;
                float bb = b0s[row], w0 = wih0s[2 * row], w1 = wih0s[2 * row + 1];
#pragma unroll
                for (int n = 0; n < 4; ++n) {
                    int b = tb + 8 * n;
                    acc[m][n] = fmaf(w0, xs[2 * b], fmaf(w1, xs[2 * b + 1], bb));
                }
            }
            accum_panel(WT, h0s, tj, tb, acc);
            if (q == 0) {
#pragma unroll
                for (int m = 0; m < 4; ++m)
#pragma unroll
                    for (int n = 0; n < 4; ++n) t1r[m][n] = sigm(acc[m][n]);
            } else if (q == 2) {
#pragma unroll
                for (int m = 0; m < 4; ++m)
#pragma unroll
                    for (int n = 0; n < 4; ++n) t1r[m][n] *= tanhf(acc[m][n]);
            } else if (q == 1) {
#pragma unroll
                for (int m = 0; m < 4; ++m)
#pragma unroll
                    for (int n = 0; n < 4; ++n)
                        c0r[m][n] = fmaf(sigm(acc[m][n]), c0r[m][n], t1r[m][n]);
            } else {
                __syncthreads();   // everyone done reading old h0 before overwrite
#pragma unroll
                for (int m = 0; m < 4; ++m)
#pragma unroll
                    for (int n = 0; n < 4; ++n) {
                        int j = tj + 32 * m, b = tb + 8 * n;
                        float hn = sigm(acc[m][n]) * tanhf(c0r[m][n]);
                        h0s[b * HH + j] = hn;
                        float u = enc_u[((size_t)t * BTOT + bbase + b) * HH + j];
                        yss[b * HH + j] = (u >= 0.3f) ? hn * DSC : 0.0f;
                    }
            }
        }
        // ---------------- layer 1 (input ys, state h1/c1) ----------------
        for (int qq = 0; qq < 4; ++qq) {
            int q = ((qq & 1) << 1) | (qq >> 1);
            __syncthreads();
            stage_chunk(WT, Wih1 + (size_t)q * 128 * HH, tid);
            __syncthreads();
            float acc[4][4];
#pragma unroll
            for (int m = 0; m < 4; ++m) {
                int row = q * 128 + tj + 32 * m;
                float bb = b1s[row];
#pragma unroll
                for (int n = 0; n < 4; ++n) acc[m][n] = bb;
            }
            accum_panel(WT, yss, tj, tb, acc);
            __syncthreads();
            stage_chunk(WT, Whh1 + (size_t)q * 128 * HH, tid);
            __syncthreads();
            accum_panel(WT, h1s, tj, tb, acc);
            if (q == 0) {
#pragma unroll
                for (int m = 0; m < 4; ++m)
#pragma unroll
                    for (int n = 0; n < 4; ++n) t1r[m][n] = sigm(acc[m][n]);
            } else if (q == 2) {
#pragma unroll
                for (int m = 0; m < 4; ++m)
#pragma unroll
                    for (int n = 0; n < 4; ++n) t1r[m][n] *= tanhf(acc[m][n]);
            } else if (q == 1) {
#pragma unroll
                for (int m = 0; m < 4; ++m)
#pragma unroll
                    for (int n = 0; n < 4; ++n)
                        c1r[m][n] = fmaf(sigm(acc[m][n]), c1r[m][n], t1r[m][n]);
            } else {
                __syncthreads();
#pragma unroll
                for (int m = 0; m < 4; ++m)
#pragma unroll
                    for (int n = 0; n < 4; ++n) {
                        int j = tj + 32 * m, b = tb + 8 * n;
                        float hn = sigm(acc[m][n]) * tanhf(c1r[m][n]);
                        h1s[b * HH + j] = hn;
                    }
            }
        }
    }

    // ============================ decoder =============================
    // h = drop(h1, hn_u); c = c1 (already in regs)
#pragma unroll
    for (int m = 0; m < 4; ++m)
#pragma unroll
        for (int n = 0; n < 4; ++n) {
            int j = tj + 32 * m, b = tb + 8 * n;
            float u = hn_u[(size_t)(bbase + b) * HH + j];
            float v = h1s[b * HH + j];
            h1s[b * HH + j] = (u >= 0.3f) ? v * DSC : 0.0f;
        }
    if (tid < NB * DD) {
        int b = tid >> 1, d = tid & 1;
        inp[tid] = obs[((size_t)(bbase + b) * TT + (TT - 1)) * DD + d];
    }

    for (int p = 0; p < PLL; ++p) {
        for (int qq = 0; qq < 4; ++qq) {
            int q = ((qq & 1) << 1) | (qq >> 1);
            __syncthreads();
            stage_chunk(WT, Whhc + (size_t)q * 128 * HH, tid);
            __syncthreads();
            float acc[4][4];
#pragma unroll
            for (int m = 0; m < 4; ++m) {
                int row = q * 128 + tj + 32 * m;
                float bb = bcs[row], w0 = wihcs[2 * row], w1 = wihcs[2 * row + 1];
#pragma unroll
                for (int n = 0; n < 4; ++n) {
                    int b = tb + 8 * n;
                    acc[m][n] = fmaf(w0, inp[2 * b], fmaf(w1, inp[2 * b + 1], bb));
                }
            }
            accum_panel(WT, h1s, tj, tb, acc);
            if (q == 0) {
#pragma unroll
                for (int m = 0; m < 4; ++m)
#pragma unroll
                    for (int n = 0; n < 4; ++n) t1r[m][n] = sigm(acc[m][n]);
            } else if (q == 2) {
#pragma unroll
                for (int m = 0; m < 4; ++m)
#pragma unroll
                    for (int n = 0; n < 4; ++n) t1r[m][n] *= tanhf(acc[m][n]);
            } else if (q == 1) {
#pragma unroll
                for (int m = 0; m < 4; ++m)
#pragma unroll
                    for (int n = 0; n < 4; ++n)
                        c1r[m][n] = fmaf(sigm(acc[m][n]), c1r[m][n], t1r[m][n]);
            } else {
                __syncthreads();
#pragma unroll
                for (int m = 0; m < 4; ++m)
#pragma unroll
                    for (int n = 0; n < 4; ++n) {
                        int j = tj + 32 * m, b = tb + 8 * n;
                        float hn = sigm(acc[m][n]) * tanhf(c1r[m][n]);
                        float u = dec_u[((size_t)p * BTOT + bbase + b) * HH + j];
                        h1s[b * HH + j] = (u >= 0.3f) ? hn * DSC : 0.0f;
                    }
            }
        }
        __syncthreads();   // h1s fully updated before cross-thread output dots
        // out = h @ Wout.T + bout ; also becomes next decoder input
        {
            int dd = tid >> 2, part = tid & 3;   // dd in 0..63: (b, o)
            int b = dd >> 1, o = dd & 1;
            const float* hr = h1s + b * HH;
            const float* wr = wouts + o * HH;
            float s = 0.0f;
#pragma unroll
            for (int j = 0; j < 32; ++j)
                s = fmaf(wr[part * 32 + j], hr[part * 32 + j], s);
            s += __shfl_xor_sync(0xffffffffu, s, 1);
            s += __shfl_xor_sync(0xffffffffu, s, 2);
            if (part == 0) {
                float val = s + bouts[o];
                out[((size_t)(bbase + b) * PLL + p) * OO + o] = val;
                inp[b * OO + o] = val;
            }
        }
        // next iteration's pre-stage __syncthreads orders inp writes vs reads
    }
}

extern "C" void kernel_launch(void* const* d_in, const int* in_sizes, int n_in,
                              void* d_out, int out_size)
{
    (void)in_sizes; (void)n_in; (void)out_size;
    const float* obs   = (const float*)d_in[0];
    const float* Wih0  = (const float*)d_in[1];
    const float* Whh0  = (const float*)d_in[2];
    const float* bih0  = (const float*)d_in[3];
    const float* bhh0  = (const float*)d_in[4];
    const float* Wih1  = (const float*)d_in[5];
    const float* Whh1  = (const float*)d_in[6];
    const float* bih1  = (const float*)d_in[7];
    const float* bhh1  = (const float*)d_in[8];
    const float* Wihc  = (const float*)d_in[9];
    const float* Whhc  = (const float*)d_in[10];
    const float* bihc  = (const float*)d_in[11];
    const float* bhhc  = (const float*)d_in[12];
    const float* Wout  = (const float*)d_in[13];
    const float* bout  = (const float*)d_in[14];
    const float* enc_u = (const float*)d_in[15];
    const float* hn_u  = (const float*)d_in[16];
    const float* dec_u = (const float*)d_in[17];
    float* out = (float*)d_out;

    cudaFuncSetAttribute(mcdlstm_kernel,
                         cudaFuncAttributeMaxDynamicSharedMemorySize, SMEM_BYTES);
    mcdlstm_kernel<<<BTOT / NB, NTH, SMEM_BYTES>>>(
        obs, Wih0, Whh0, bih0, bhh0, Wih1, Whh1, bih1, bhh1,
        Wihc, Whhc, bihc, bhhc, Wout, bout, enc_u, hn_u, dec_u, out);
}

// round 2
// speedup vs baseline: 1.0039x; 1.0039x over previous
#include <cuda_runtime.h>
#include <math.h>

// Problem constants
#define BTOT   32768
#define TT     32
#define DD     2
#define HH     128
#define GG     512
#define PLL    12
#define OO     2

// Tiling
#define NB     32          // batch elements per CTA
#define NTH    256         // threads per CTA
#define WPITCH 129         // padded smem pitch for transposed weight chunk

// smem layout (floats)
#define OFF_H0    0        // 4096  h0 state   [NB][HH]
#define OFF_H1    4096     // 4096  h1 state   [NB][HH]
#define OFF_YS    8192     // 4096  ys (dropped layer0 out)
#define OFF_WT    12288    // 16512 transposed weight chunk [128][WPITCH]
#define OFF_B0    28800    // 512   combined bias layer0
#define OFF_B1    29312    // 512   combined bias layer1
#define OFF_BC    29824    // 512   combined bias decoder cell
#define OFF_WIH0  30336    // 1024  Wih0 (512x2)
#define OFF_WIHC  31360    // 1024  Wihc (512x2)
#define OFF_WOUT  32384    // 256   Wout (2x128)
#define OFF_BOUT  32640    // 4     bout
#define OFF_XS    32644    // 64    x_t   [NB][2]
#define OFF_INP   32708    // 64    decoder input [NB][2]
#define SMEM_FLOATS 32772
#define SMEM_BYTES  (SMEM_FLOATS * 4)

static __device__ __forceinline__ float sigm(float x) {
    return 1.0f / (1.0f + expf(-x));
}

// Stage a 128-row x 128-col fp32 weight chunk from global (row-major) into
// transposed smem WT[k][j] with pitch 129 (conflict-free reads & writes).
static __device__ __forceinline__ void stage_chunk(float* __restrict__ WT,
                                                   const float* __restrict__ src,
                                                   int tid)
{
#pragma unroll
    for (int i = 0; i < 64; ++i) {
        int idx = tid + i * NTH;         // 0..16383
        int j = idx >> 7;                // row (gate unit within chunk)
        int k = idx & 127;               // col (k index)
        WT[k * WPITCH + j] = src[idx];   // coalesced LDG, conflict-free STS
    }
}

// acc[m][n] += sum_k WT[k][tj+32m] * hb[(tb+8n)*HH + k]
static __device__ __forceinline__ void accum_panel(const float* __restrict__ WT,
                                                   const float* __restrict__ hb,
                                                   int tj, int tb,
                                                   float (&acc)[4][4])
{
#pragma unroll 4
    for (int k4 = 0; k4 < 32; ++k4) {
        float hv[4][4];
#pragma unroll
        for (int n = 0; n < 4; ++n) {
            float4 v = reinterpret_cast<const float4*>(hb + (tb + 8 * n) * HH)[k4];
            hv[n][0] = v.x; hv[n][1] = v.y; hv[n][2] = v.z; hv[n][3] = v.w;
        }
#pragma unroll
        for (int d = 0; d < 4; ++d) {
            float w[4];
#pragma unroll
            for (int m = 0; m < 4; ++m)
                w[m] = WT[(4 * k4 + d) * WPITCH + tj + 32 * m];
#pragma unroll
            for (int m = 0; m < 4; ++m)
#pragma unroll
                for (int n = 0; n < 4; ++n)
                    acc[m][n] = fmaf(w[m], hv[n][d], acc[m][n]);
        }
    }
}

__global__ void __launch_bounds__(NTH, 1)
mcdlstm_kernel(const float* __restrict__ obs,
               const float* __restrict__ Wih0, const float* __restrict__ Whh0,
               const float* __restrict__ bih0, const float* __restrict__ bhh0,
               const float* __restrict__ Wih1, const float* __restrict__ Whh1,
               const float* __restrict__ bih1, const float* __restrict__ bhh1,
               const float* __restrict__ Wihc, const float* __restrict__ Whhc,
               const float* __restrict__ bihc, const float* __restrict__ bhhc,
               const float* __restrict__ Wout, const float* __restrict__ bout,
               const float* __restrict__ enc_u, const float* __restrict__ hn_u,
               const float* __restrict__ dec_u,
               float* __restrict__ out)
{
    extern __shared__ float sm[];
    float* h0s   = sm + OFF_H0;
    float* h1s   = sm + OFF_H1;
    float* yss   = sm + OFF_YS;
    float* WT    = sm + OFF_WT;
    float* b0s   = sm + OFF_B0;
    float* b1s   = sm + OFF_B1;
    float* bcs   = sm + OFF_BC;
    float* wih0s = sm + OFF_WIH0;
    float* wihcs = sm + OFF_WIHC;
    float* wouts = sm + OFF_WOUT;
    float* bouts = sm + OFF_BOUT;
    float* xs    = sm + OFF_XS;
    float* inp   = sm + OFF_INP;

    const int tid = threadIdx.x;
    const int tj  = tid & 31;   // gate-unit lane: j = tj + 32*m
    const int tb  = tid >> 5;   // batch lane:     b = tb + 8*n
    const int bbase = blockIdx.x * NB;
    const float DSC = (float)(1.0 / 0.7);   // dropout scale 1/(1-P)

    // --- init ---
    for (int i = tid; i < 8192; i += NTH) sm[i] = 0.0f;   // h0s, h1s
    for (int i = tid; i < GG; i += NTH) {
        b0s[i] = bih0[i] + bhh0[i];
        b1s[i] = bih1[i] + bhh1[i];
        bcs[i] = bihc[i] + bhhc[i];
    }
    for (int i = tid; i < GG * 2; i += NTH) {
        wih0s[i] = Wih0[i];
        wihcs[i] = Wihc[i];
    }
    if (tid < OO * HH) wouts[tid] = Wout[tid];
    if (tid < OO)      bouts[tid] = bout[tid];

    float c0r[4][4], c1r[4][4], t1r[4][4];
#pragma unroll
    for (int m = 0; m < 4; ++m)
#pragma unroll
        for (int n = 0; n < 4; ++n) { c0r[m][n] = 0.0f; c1r[m][n] = 0.0f; t1r[m][n] = 0.0f; }

    // ======================= encoder: 32 time steps =======================
    for (int t = 0; t < TT; ++t) {
        if (tid < NB * DD) {
            int b = tid >> 1, d = tid & 1;
            xs[tid] = obs[((size_t)(bbase + b) * TT + t) * DD + d];
        }
        // ---------------- layer 0 (input x_t, state h0/c0) ----------------
        for (int qq = 0; qq < 4; ++qq) {
            int q = ((qq & 1) << 1) | (qq >> 1);   // pass order: i(0), g(2), f(1), o(3)
            __syncthreads();
            stage_chunk(WT, Whh0 + (size_t)q * 128 * HH, tid);
            __syncthreads();
            float acc[4][4];
#pragma unroll
            for (int m = 0; m < 4; ++m) {
                int row = q * 128 + tj + 32 * m;
                float bb = b0s[row], w0 = wih0s[2 * row], w1 = wih0s[2 * row + 1];
#pragma unroll
                for (int n = 0; n < 4; ++n) {
                    int b = tb + 8 * n;
                    acc[m][n] = fmaf(w0, xs[2 * b], fmaf(w1, xs[2 * b + 1], bb));
                }
            }
            accum_panel(WT, h0s, tj, tb, acc);
            if (q == 0) {
#pragma unroll
                for (int m = 0; m < 4; ++m)
#pragma unroll
                    for (int n = 0; n < 4; ++n) t1r[m][n] = sigm(acc[m][n]);
            } else if (q == 2) {
#pragma unroll
                for (int m = 0; m < 4; ++m)
#pragma unroll
                    for (int n = 0; n < 4; ++n) t1r[m][n] *= tanhf(acc[m][n]);
            } else if (q == 1) {
#pragma unroll
                for (int m = 0; m < 4; ++m)
#pragma unroll
                    for (int n = 0; n < 4; ++n)
                        c0r[m][n] = fmaf(sigm(acc[m][n]), c0r[m][n], t1r[m][n]);
            } else {
                __syncthreads();   // everyone done reading old h0 before overwrite
#pragma unroll
                for (int m = 0; m < 4; ++m)
#pragma unroll
                    for (int n = 0; n < 4; ++n) {
                        int j = tj + 32 * m, b = tb + 8 * n;
                        float hn = sigm(acc[m][n]) * tanhf(c0r[m][n]);
                        h0s[b * HH + j] = hn;
                        float u = enc_u[((size_t)t * BTOT + bbase + b) * HH + j];
                        yss[b * HH + j] = (u >= 0.3f) ? hn * DSC : 0.0f;
                    }
            }
        }
        // ---------------- layer 1 (input ys, state h1/c1) ----------------
        for (int qq = 0; qq < 4; ++qq) {
            int q = ((qq & 1) << 1) | (qq >> 1);
            __syncthreads();
            stage_chunk(WT, Wih1 + (size_t)q * 128 * HH, tid);
            __syncthreads();
            float acc[4][4];
#pragma unroll
            for (int m = 0; m < 4; ++m) {
                int row = q * 128 + tj + 32 * m;
                float bb = b1s[row];
#pragma unroll
                for (int n = 0; n < 4; ++n) acc[m][n] = bb;
            }
            accum_panel(WT, yss, tj, tb, acc);
            __syncthreads();
            stage_chunk(WT, Whh1 + (size_t)q * 128 * HH, tid);
            __syncthreads();
            accum_panel(WT, h1s, tj, tb, acc);
            if (q == 0) {
#pragma unroll
                for (int m = 0; m < 4; ++m)
#pragma unroll
                    for (int n = 0; n < 4; ++n) t1r[m][n] = sigm(acc[m][n]);
            } else if (q == 2) {
#pragma unroll
                for (int m = 0; m < 4; ++m)
#pragma unroll
                    for (int n = 0; n < 4; ++n) t1r[m][n] *= tanhf(acc[m][n]);
            } else if (q == 1) {
#pragma unroll
                for (int m = 0; m < 4; ++m)
#pragma unroll
                    for (int n = 0; n < 4; ++n)
                        c1r[m][n] = fmaf(sigm(acc[m][n]), c1r[m][n], t1r[m][n]);
            } else {
                __syncthreads();
#pragma unroll
                for (int m = 0; m < 4; ++m)
#pragma unroll
                    for (int n = 0; n < 4; ++n) {
                        int j = tj + 32 * m, b = tb + 8 * n;
                        float hn = sigm(acc[m][n]) * tanhf(c1r[m][n]);
                        h1s[b * HH + j] = hn;
                    }
            }
        }
    }

    // ============================ decoder =============================
    // h = drop(h1, hn_u); c = c1 (already in regs)
#pragma unroll
    for (int m = 0; m < 4; ++m)
#pragma unroll
        for (int n = 0; n < 4; ++n) {
            int j = tj + 32 * m, b = tb + 8 * n;
            float u = hn_u[(size_t)(bbase + b) * HH + j];
            float v = h1s[b * HH + j];
            h1s[b * HH + j] = (u >= 0.3f) ? v * DSC : 0.0f;
        }
    if (tid < NB * DD) {
        int b = tid >> 1, d = tid & 1;
        inp[tid] = obs[((size_t)(bbase + b) * TT + (TT - 1)) * DD + d];
    }

    for (int p = 0; p < PLL; ++p) {
        for (int qq = 0; qq < 4; ++qq) {
            int q = ((qq & 1) << 1) | (qq >> 1);
            __syncthreads();
            stage_chunk(WT, Whhc + (size_t)q * 128 * HH, tid);
            __syncthreads();
            float acc[4][4];
#pragma unroll
            for (int m = 0; m < 4; ++m) {
                int row = q * 128 + tj + 32 * m;
                float bb = bcs[row], w0 = wihcs[2 * row], w1 = wihcs[2 * row + 1];
#pragma unroll
                for (int n = 0; n < 4; ++n) {
                    int b = tb + 8 * n;
                    acc[m][n] = fmaf(w0, inp[2 * b], fmaf(w1, inp[2 * b + 1], bb));
                }
            }
            accum_panel(WT, h1s, tj, tb, acc);
            if (q == 0) {
#pragma unroll
                for (int m = 0; m < 4; ++m)
#pragma unroll
                    for (int n = 0; n < 4; ++n) t1r[m][n] = sigm(acc[m][n]);
            } else if (q == 2) {
#pragma unroll
                for (int m = 0; m < 4; ++m)
#pragma unroll
                    for (int n = 0; n < 4; ++n) t1r[m][n] *= tanhf(acc[m][n]);
            } else if (q == 1) {
#pragma unroll
                for (int m = 0; m < 4; ++m)
#pragma unroll
                    for (int n = 0; n < 4; ++n)
                        c1r[m][n] = fmaf(sigm(acc[m][n]), c1r[m][n], t1r[m][n]);
            } else {
                __syncthreads();
#pragma unroll
                for (int m = 0; m < 4; ++m)
#pragma unroll
                    for (int n = 0; n < 4; ++n) {
                        int j = tj + 32 * m, b = tb + 8 * n;
                        float hn = sigm(acc[m][n]) * tanhf(c1r[m][n]);
                        float u = dec_u[((size_t)p * BTOT + bbase + b) * HH + j];
                        h1s[b * HH + j] = (u >= 0.3f) ? hn * DSC : 0.0f;
                    }
            }
        }
        __syncthreads();   // h1s fully updated before cross-thread output dots
        // out = h @ Wout.T + bout ; also becomes next decoder input
        {
            int dd = tid >> 2, part = tid & 3;   // dd in 0..63: (b, o)
            int b = dd >> 1, o = dd & 1;
            const float* hr = h1s + b * HH;
            const float* wr = wouts + o * HH;
            float s = 0.0f;
#pragma unroll
            for (int j = 0; j < 32; ++j)
                s = fmaf(wr[part * 32 + j], hr[part * 32 + j], s);
            s += __shfl_xor_sync(0xffffffffu, s, 1);
            s += __shfl_xor_sync(0xffffffffu, s, 2);
            if (part == 0) {
                float val = s + bouts[o];
                out[((size_t)(bbase + b) * PLL + p) * OO + o] = val;
                inp[b * OO + o] = val;
            }
        }
        // next iteration's pre-stage __syncthreads orders inp writes vs reads
    }
}

extern "C" void kernel_launch(void* const* d_in, const int* in_sizes, int n_in,
                              void* d_out, int out_size)
{
    (void)in_sizes; (void)n_in; (void)out_size;
    const float* obs   = (const float*)d_in[0];
    const float* Wih0  = (const float*)d_in[1];
    const float* Whh0  = (const float*)d_in[2];
    const float* bih0  = (const float*)d_in[3];
    const float* bhh0  = (const float*)d_in[4];
    const float* Wih1  = (const float*)d_in[5];
    const float* Whh1  = (const float*)d_in[6];
    const float* bih1  = (const float*)d_in[7];
    const float* bhh1  = (const float*)d_in[8];
    const float* Wihc  = (const float*)d_in[9];
    const float* Whhc  = (const float*)d_in[10];
    const float* bihc  = (const float*)d_in[11];
    const float* bhhc  = (const float*)d_in[12];
    const float* Wout  = (const float*)d_in[13];
    const float* bout  = (const float*)d_in[14];
    const float* enc_u = (const float*)d_in[15];
    const float* hn_u  = (const float*)d_in[16];
    const float* dec_u = (const float*)d_in[17];
    float* out = (float*)d_out;

    cudaFuncSetAttribute(mcdlstm_kernel,
                         cudaFuncAttributeMaxDynamicSharedMemorySize, SMEM_BYTES);
    mcdlstm_kernel<<<BTOT / NB, NTH, SMEM_BYTES>>>(
        obs, Wih0, Whh0, bih0, bhh0, Wih1, Whh1, bih1, bhh1,
        Wihc, Whhc, bihc, bhhc, Wout, bout, enc_u, hn_u, dec_u, out);
}

// round 3
// speedup vs baseline: 3.6695x; 3.6552x over previous
#include <cuda_runtime.h>
#include <cuda_bf16.h>
#include <math.h>
#include <stdint.h>

#define BTOT 32768
#define TT   32
#define HH   128
#define GG   512
#define PLL  12
#define OO   2
#define NB   64
#define NTH  256

// smem byte offsets: six 16KB A-buffers (bf16, swizzled), 4x16KB weight stage, fp32 region
#define A_H0H 0u
#define A_H0L 16384u
#define A_YSH 32768u
#define A_YSL 49152u
#define A_H1H 65536u
#define A_H1L 81920u
#define WSOFF 98304u
#define FOFF  163840u
#define SMEM_BYTES (163840 + 16400)

// fp32 region float indices
#define F_B0   0
#define F_B1   512
#define F_BC   1024
#define F_WIH0 1536
#define F_WIHC 2560
#define F_WOUT 3584
#define F_BOUT 3840
#define F_XS   3844
#define F_INP  3972

// weight matrices: 0=Whh0 1=Wih1 2=Whh1 3=Whhc  (bf16 hi/lo split, L2-resident)
__device__ __align__(128) __nv_bfloat16 g_Whi[4][GG * HH];
__device__ __align__(128) __nv_bfloat16 g_Wlo[4][GG * HH];

__global__ void prep_kernel(const float* __restrict__ Whh0, const float* __restrict__ Wih1,
                            const float* __restrict__ Whh1, const float* __restrict__ Whhc)
{
    int idx = blockIdx.x * blockDim.x + threadIdx.x;   // 0..65535
    const float* src[4] = {Whh0, Wih1, Whh1, Whhc};
#pragma unroll
    for (int m = 0; m < 4; ++m) {
        float v = src[m][idx];
        __nv_bfloat16 hi = __float2bfloat16(v);
        g_Whi[m][idx] = hi;
        g_Wlo[m][idx] = __float2bfloat16(v - __bfloat162float(hi));
    }
}

static __device__ __forceinline__ uint32_t smem_u32(const void* p) {
    uint32_t a;
    asm("{ .reg .u64 t; cvta.to.shared.u64 t, %1; cvt.u32.u64 %0, t; }" : "=r"(a) : "l"(p));
    return a;
}
static __device__ __forceinline__ float sigm(float x) {
    return __fdividef(1.0f, 1.0f + __expf(-x));
}
static __device__ __forceinline__ float tanhfast(float x) {
    float e = __expf(-2.0f * fabsf(x));
    float r = __fdividef(1.0f - e, 1.0f + e);
    return copysignf(r, x);
}

// byte offset of element (m,k) in a [64 rows][128 k] bf16 A-buffer
// (256B rows, 16B-chunk XOR swizzle -> conflict-free ldmatrix)
static __device__ __forceinline__ uint32_t abyte(uint32_t m, uint32_t k) {
    return m * 256u + ((((k >> 3) ^ (m & 7)) << 4)) + ((k & 7) << 1);
}

static __device__ __forceinline__ void st_split(char* smc, uint32_t bH, uint32_t bL,
                                                uint32_t m, uint32_t j0, float v0, float v1)
{
    uint32_t off = abyte(m, j0);
    __nv_bfloat16 h0 = __float2bfloat16(v0);
    __nv_bfloat16 h1 = __float2bfloat16(v1);
    __nv_bfloat162 hp; hp.x = h0; hp.y = h1;
    __nv_bfloat162 lp;
    lp.x = __float2bfloat16(v0 - __bfloat162float(h0));
    lp.y = __float2bfloat16(v1 - __bfloat162float(h1));
    *(__nv_bfloat162*)(smc + bH + off) = hp;
    *(__nv_bfloat162*)(smc + bL + off) = lp;
}

static __device__ __forceinline__ void ldsm4(uint32_t& r0, uint32_t& r1,
                                             uint32_t& r2, uint32_t& r3, uint32_t addr)
{
    asm volatile("ldmatrix.sync.aligned.m8n8.x4.shared.b16 {%0,%1,%2,%3}, [%4];\n"
                 : "=r"(r0), "=r"(r1), "=r"(r2), "=r"(r3) : "r"(addr));
}
static __device__ __forceinline__ void mma16816(float* c,
    uint32_t a0, uint32_t a1, uint32_t a2, uint32_t a3, uint32_t b0, uint32_t b1)
{
    asm volatile("mma.sync.aligned.m16n8k16.row.col.f32.bf16.bf16.f32 "
                 "{%0,%1,%2,%3}, {%4,%5,%6,%7}, {%8,%9}, {%0,%1,%2,%3};\n"
                 : "+f"(c[0]), "+f"(c[1]), "+f"(c[2]), "+f"(c[3])
                 : "r"(a0), "r"(a1), "r"(a2), "r"(a3), "r"(b0), "r"(b1));
}

// stage a [128 n][64 k] hi+lo bf16 weight slab into stage buffer sbuf (cp.async, 16B)
static __device__ __forceinline__ void issue_stage(uint32_t ws, int sbuf,
    const __nv_bfloat16* gh, const __nv_bfloat16* gl, int tid)
{
    uint32_t dsth = ws + (uint32_t)(sbuf * 2) * 16384u;
    uint32_t dstl = dsth + 16384u;
#pragma unroll
    for (int i = 0; i < 4; ++i) {
        uint32_t c = (uint32_t)(tid + i * NTH);      // 0..1023
        uint32_t n = c >> 3, kc = c & 7;
        uint32_t off = n * 128u + ((kc ^ (n & 7)) << 4);
        size_t gsh = __cvta_generic_to_global(gh + n * HH + kc * 8);
        size_t gsl = __cvta_generic_to_global(gl + n * HH + kc * 8);
        asm volatile("cp.async.cg.shared.global [%0], [%1], 16;\n" :: "r"(dsth + off), "l"(gsh));
        asm volatile("cp.async.cg.shared.global [%0], [%1], 16;\n" :: "r"(dstl + off), "l"(gsl));
    }
    asm volatile("cp.async.commit_group;\n");
}

// consume one staged k64 slab: 4 k16 steps, 8 n8 tiles, 3-term bf16-split MMA
static __device__ __forceinline__ void consume_stage(float (&acc)[8][4],
    uint32_t whi, uint32_t wlo, uint32_t ahi, uint32_t alo, int akbase,
    int lane, int mw, int nw)
{
    uint32_t arow = (uint32_t)(mw * 16 + (lane & 15));
    uint32_t aswz = (arow & 7) << 4;
    uint32_t arow_off = arow * 256u;
    uint32_t achunk_add = (uint32_t)(lane >> 4);
    uint32_t brow0 = (uint32_t)(nw * 64 + (lane & 7) + ((lane >> 4) << 3));
    uint32_t bswz = (uint32_t)(lane & 7) << 4;
    uint32_t bk_half = (uint32_t)((lane >> 3) & 1);
#pragma unroll
    for (int ks = 0; ks < 4; ++ks) {
        uint32_t achunk = (uint32_t)(((akbase + ks * 16) >> 3) + achunk_add) << 4;
        uint32_t aoff = arow_off + (achunk ^ aswz);
        uint32_t a0, a1, a2, a3, l0, l1, l2, l3;
        ldsm4(a0, a1, a2, a3, ahi + aoff);
        ldsm4(l0, l1, l2, l3, alo + aoff);
        uint32_t bko = ((uint32_t)(ks * 2) + bk_half) << 4;
#pragma unroll
        for (int g = 0; g < 4; ++g) {
            uint32_t n = brow0 + (uint32_t)g * 16u;
            uint32_t boff = n * 128u + (bko ^ bswz);
            uint32_t bh0, bh1, bh2, bh3, bl0, bl1, bl2, bl3;
            ldsm4(bh0, bh1, bh2, bh3, whi + boff);
            ldsm4(bl0, bl1, bl2, bl3, wlo + boff);
            mma16816(acc[2 * g],     a0, a1, a2, a3, bh0, bh1);
            mma16816(acc[2 * g],     a0, a1, a2, a3, bl0, bl1);
            mma16816(acc[2 * g],     l0, l1, l2, l3, bh0, bh1);
            mma16816(acc[2 * g + 1], a0, a1, a2, a3, bh2, bh3);
            mma16816(acc[2 * g + 1], a0, a1, a2, a3, bl2, bl3);
            mma16816(acc[2 * g + 1], l0, l1, l2, l3, bh2, bh3);
        }
    }
}

template<int NS>
static __device__ __forceinline__ void gemm_pass(float (&acc)[8][4],
    const __nv_bfloat16* const* gh, const __nv_bfloat16* const* gl,
    const uint32_t* ah, const uint32_t* al, const int* akb,
    uint32_t ws, int tid, int lane, int mw, int nw)
{
    __syncthreads();                        // prior A-writes visible; stage bufs free
    issue_stage(ws, 0, gh[0], gl[0], tid);
    issue_stage(ws, 1, gh[1], gl[1], tid);
#pragma unroll
    for (int s = 0; s < NS; ++s) {
        if (s == NS - 1) asm volatile("cp.async.wait_group 0;\n" ::: "memory");
        else             asm volatile("cp.async.wait_group 1;\n" ::: "memory");
        __syncthreads();
        uint32_t whi = ws + (uint32_t)((s & 1) * 2) * 16384u;
        consume_stage(acc, whi, whi + 16384u, ah[s], al[s], akb[s], lane, mw, nw);
        if (s + 2 < NS) {
            __syncthreads();                // all warps done with buffer s
            issue_stage(ws, s & 1, gh[s + 2], gl[s + 2], tid);
        }
    }
}

// acc init: bias (+ optional [*,2] input GEMM in fp32)
static __device__ __forceinline__ void init_acc(float (&acc)[8][4], const float* bq,
    const float* wq, const float* xv, int lane, int mw, int nw)
{
    float2 x0 = make_float2(0.f, 0.f), x1 = x0;
    if (wq) {
        int m0 = mw * 16 + (lane >> 2);
        x0 = *(const float2*)(xv + 2 * m0);
        x1 = *(const float2*)(xv + 2 * (m0 + 8));
    }
#pragma unroll
    for (int t = 0; t < 8; ++t) {
        int j0 = nw * 64 + t * 8 + (lane & 3) * 2;
        float2 bb = *(const float2*)(bq + j0);
        if (wq) {
            float2 w0 = *(const float2*)(wq + 2 * j0);
            float2 w1 = *(const float2*)(wq + 2 * j0 + 2);
            acc[t][0] = bb.x + w0.x * x0.x + w0.y * x0.y;
            acc[t][1] = bb.y + w1.x * x0.x + w1.y * x0.y;
            acc[t][2] = bb.x + w0.x * x1.x + w0.y * x1.y;
            acc[t][3] = bb.y + w1.x * x1.x + w1.y * x1.y;
        } else {
            acc[t][0] = bb.x; acc[t][1] = bb.y;
            acc[t][2] = bb.x; acc[t][3] = bb.y;
        }
    }
}

__global__ void __launch_bounds__(NTH, 1)
mcdlstm_kernel(const float* __restrict__ obs,
               const float* __restrict__ Wih0,
               const float* __restrict__ bih0, const float* __restrict__ bhh0,
               const float* __restrict__ bih1, const float* __restrict__ bhh1,
               const float* __restrict__ Wihc,
               const float* __restrict__ bihc, const float* __restrict__ bhhc,
               const float* __restrict__ Wout, const float* __restrict__ bout,
               const float* __restrict__ enc_u, const float* __restrict__ hn_u,
               const float* __restrict__ dec_u,
               float* __restrict__ out)
{
    extern __shared__ char smc[];
    float* F = (float*)(smc + FOFF);
    const uint32_t smb = smem_u32(smc);
    const uint32_t ws  = smb + WSOFF;
    const uint32_t aH0H = smb + A_H0H, aH0L = smb + A_H0L;
    const uint32_t aYSH = smb + A_YSH, aYSL = smb + A_YSL;
    const uint32_t aH1H = smb + A_H1H, aH1L = smb + A_H1L;

    const int tid  = threadIdx.x;
    const int lane = tid & 31;
    const int wid  = tid >> 5;
    const int mw   = wid & 3;        // 0..3 -> batch rows mw*16..+15
    const int nw   = wid >> 2;       // 0..1 -> gate cols nw*64..+63
    const int bbase = blockIdx.x * NB;
    const float DSC = (float)(1.0 / 0.7);

    // ---- init: zero state buffers, load biases & small weights ----
    for (int i = tid; i < 98304 / 4; i += NTH) ((uint32_t*)smc)[i] = 0u;
    for (int i = tid; i < GG; i += NTH) {
        F[F_B0 + i] = bih0[i] + bhh0[i];
        F[F_B1 + i] = bih1[i] + bhh1[i];
        F[F_BC + i] = bihc[i] + bhhc[i];
    }
    for (int i = tid; i < GG * 2; i += NTH) {
        F[F_WIH0 + i] = Wih0[i];
        F[F_WIHC + i] = Wihc[i];
    }
    if (tid < OO * HH) F[F_WOUT + tid] = Wout[tid];
    if (tid < OO)      F[F_BOUT + tid] = bout[tid];

    float c0r[8][4], c1r[8][4], t1r[8][4], acc[8][4];
#pragma unroll
    for (int t = 0; t < 8; ++t)
#pragma unroll
        for (int r = 0; r < 4; ++r) { c0r[t][r] = 0.f; c1r[t][r] = 0.f; t1r[t][r] = 0.f; }

    // ===================== encoder =====================
#pragma unroll 1
    for (int t = 0; t < TT; ++t) {
        if (tid < NB * 2) {
            int b = tid >> 1, d = tid & 1;
            F[F_XS + tid] = obs[((size_t)(bbase + b) * TT + t) * 2 + d];
        }
        __syncthreads();

        // ---- layer 0: gates over h0 (K=128) ----
#pragma unroll 1
        for (int qq = 0; qq < 4; ++qq) {
            int q = ((qq & 1) << 1) | (qq >> 1);     // i, g, f, o
            init_acc(acc, F + F_B0 + q * 128, F + F_WIH0 + q * 256, F + F_XS, lane, mw, nw);
            const __nv_bfloat16* gh[2] = { g_Whi[0] + q * 16384, g_Whi[0] + q * 16384 + 64 };
            const __nv_bfloat16* gl[2] = { g_Wlo[0] + q * 16384, g_Wlo[0] + q * 16384 + 64 };
            uint32_t ah[2] = { aH0H, aH0H }, al[2] = { aH0L, aH0L };
            int akb[2] = { 0, 64 };
            gemm_pass<2>(acc, gh, gl, ah, al, akb, ws, tid, lane, mw, nw);
            if (q == 0) {
#pragma unroll
                for (int i = 0; i < 8; ++i)
#pragma unroll
                    for (int r = 0; r < 4; ++r) t1r[i][r] = sigm(acc[i][r]);
            } else if (q == 2) {
#pragma unroll
                for (int i = 0; i < 8; ++i)
#pragma unroll
                    for (int r = 0; r < 4; ++r) t1r[i][r] *= tanhfast(acc[i][r]);
            } else if (q == 1) {
#pragma unroll
                for (int i = 0; i < 8; ++i)
#pragma unroll
                    for (int r = 0; r < 4; ++r)
                        c0r[i][r] = fmaf(sigm(acc[i][r]), c0r[i][r], t1r[i][r]);
            } else {
                __syncthreads();   // all warps done reading h0 this pass
#pragma unroll
                for (int i = 0; i < 8; ++i) {
                    uint32_t j0 = (uint32_t)(nw * 64 + i * 8 + (lane & 3) * 2);
#pragma unroll
                    for (int hf = 0; hf < 2; ++hf) {
                        uint32_t m = (uint32_t)(mw * 16 + (lane >> 2) + hf * 8);
                        float v0 = sigm(acc[i][2 * hf])     * tanhfast(c0r[i][2 * hf]);
                        float v1 = sigm(acc[i][2 * hf + 1]) * tanhfast(c0r[i][2 * hf + 1]);
                        st_split(smc, A_H0H, A_H0L, m, j0, v0, v1);
                        float2 u = *(const float2*)(enc_u +
                            ((size_t)t * BTOT + bbase + m) * HH + j0);
                        st_split(smc, A_YSH, A_YSL, m, j0,
                                 (u.x >= 0.3f) ? v0 * DSC : 0.0f,
                                 (u.y >= 0.3f) ? v1 * DSC : 0.0f);
                    }
                }
            }
        }

        // ---- layer 1: gates over [ys ; h1] (K=256) ----
#pragma unroll 1
        for (int qq = 0; qq < 4; ++qq) {
            int q = ((qq & 1) << 1) | (qq >> 1);
            init_acc(acc, F + F_B1 + q * 128, (const float*)0, (const float*)0, lane, mw, nw);
            const __nv_bfloat16* gh[4] = { g_Whi[1] + q * 16384, g_Whi[1] + q * 16384 + 64,
                                           g_Whi[2] + q * 16384, g_Whi[2] + q * 16384 + 64 };
            const __nv_bfloat16* gl[4] = { g_Wlo[1] + q * 16384, g_Wlo[1] + q * 16384 + 64,
                                           g_Wlo[2] + q * 16384, g_Wlo[2] + q * 16384 + 64 };
            uint32_t ah[4] = { aYSH, aYSH, aH1H, aH1H };
            uint32_t al[4] = { aYSL, aYSL, aH1L, aH1L };
            int akb[4] = { 0, 64, 0, 64 };
            gemm_pass<4>(acc, gh, gl, ah, al, akb, ws, tid, lane, mw, nw);
            if (q == 0) {
#pragma unroll
                for (int i = 0; i < 8; ++i)
#pragma unroll
                    for (int r = 0; r < 4; ++r) t1r[i][r] = sigm(acc[i][r]);
            } else if (q == 2) {
#pragma unroll
                for (int i = 0; i < 8; ++i)
#pragma unroll
                    for (int r = 0; r < 4; ++r) t1r[i][r] *= tanhfast(acc[i][r]);
            } else if (q == 1) {
#pragma unroll
                for (int i = 0; i < 8; ++i)
#pragma unroll
                    for (int r = 0; r < 4; ++r)
                        c1r[i][r] = fmaf(sigm(acc[i][r]), c1r[i][r], t1r[i][r]);
            } else {
                __syncthreads();
#pragma unroll
                for (int i = 0; i < 8; ++i) {
                    uint32_t j0 = (uint32_t)(nw * 64 + i * 8 + (lane & 3) * 2);
#pragma unroll
                    for (int hf = 0; hf < 2; ++hf) {
                        uint32_t m = (uint32_t)(mw * 16 + (lane >> 2) + hf * 8);
                        float v0 = sigm(acc[i][2 * hf])     * tanhfast(c1r[i][2 * hf]);
                        float v1 = sigm(acc[i][2 * hf + 1]) * tanhfast(c1r[i][2 * hf + 1]);
                        st_split(smc, A_H1H, A_H1L, m, j0, v0, v1);
                    }
                }
            }
        }
    }

    // ===================== hn dropout on h1 =====================
    __syncthreads();
#pragma unroll
    for (int i = 0; i < 8; ++i) {
        uint32_t j0 = (uint32_t)(nw * 64 + i * 8 + (lane & 3) * 2);
#pragma unroll
        for (int hf = 0; hf < 2; ++hf) {
            uint32_t m = (uint32_t)(mw * 16 + (lane >> 2) + hf * 8);
            uint32_t off = abyte(m, j0);
            __nv_bfloat162 hp = *(__nv_bfloat162*)(smc + A_H1H + off);
            __nv_bfloat162 lp = *(__nv_bfloat162*)(smc + A_H1L + off);
            float v0 = __bfloat162float(hp.x) + __bfloat162float(lp.x);
            float v1 = __bfloat162float(hp.y) + __bfloat162float(lp.y);
            float2 u = *(const float2*)(hn_u + (size_t)(bbase + m) * HH + j0);
            st_split(smc, A_H1H, A_H1L, m, j0,
                     (u.x >= 0.3f) ? v0 * DSC : 0.0f,
                     (u.y >= 0.3f) ? v1 * DSC : 0.0f);
        }
    }
    if (tid < NB * 2) {
        int b = tid >> 1, d = tid & 1;
        F[F_INP + tid] = obs[((size_t)(bbase + b) * TT + (TT - 1)) * 2 + d];
    }
    __syncthreads();

    // ===================== decoder =====================
#pragma unroll 1
    for (int p = 0; p < PLL; ++p) {
#pragma unroll 1
        for (int qq = 0; qq < 4; ++qq) {
            int q = ((qq & 1) << 1) | (qq >> 1);
            init_acc(acc, F + F_BC + q * 128, F + F_WIHC + q * 256, F + F_INP, lane, mw, nw);
            const __nv_bfloat16* gh[2] = { g_Whi[3] + q * 16384, g_Whi[3] + q * 16384 + 64 };
            const __nv_bfloat16* gl[2] = { g_Wlo[3] + q * 16384, g_Wlo[3] + q * 16384 + 64 };
            uint32_t ah[2] = { aH1H, aH1H }, al[2] = { aH1L, aH1L };
            int akb[2] = { 0, 64 };
            gemm_pass<2>(acc, gh, gl, ah, al, akb, ws, tid, lane, mw, nw);
            if (q == 0) {
#pragma unroll
                for (int i = 0; i < 8; ++i)
#pragma unroll
                    for (int r = 0; r < 4; ++r) t1r[i][r] = sigm(acc[i][r]);
            } else if (q == 2) {
#pragma unroll
                for (int i = 0; i < 8; ++i)
#pragma unroll
                    for (int r = 0; r < 4; ++r) t1r[i][r] *= tanhfast(acc[i][r]);
            } else if (q == 1) {
#pragma unroll
                for (int i = 0; i < 8; ++i)
#pragma unroll
                    for (int r = 0; r < 4; ++r)
                        c1r[i][r] = fmaf(sigm(acc[i][r]), c1r[i][r], t1r[i][r]);
            } else {
                __syncthreads();
#pragma unroll
                for (int i = 0; i < 8; ++i) {
                    uint32_t j0 = (uint32_t)(nw * 64 + i * 8 + (lane & 3) * 2);
#pragma unroll
                    for (int hf = 0; hf < 2; ++hf) {
                        uint32_t m = (uint32_t)(mw * 16 + (lane >> 2) + hf * 8);
                        float v0 = sigm(acc[i][2 * hf])     * tanhfast(c1r[i][2 * hf]);
                        float v1 = sigm(acc[i][2 * hf + 1]) * tanhfast(c1r[i][2 * hf + 1]);
                        float2 u = *(const float2*)(dec_u +
                            ((size_t)p * BTOT + bbase + m) * HH + j0);
                        st_split(smc, A_H1H, A_H1L, m, j0,
                                 (u.x >= 0.3f) ? v0 * DSC : 0.0f,
                                 (u.y >= 0.3f) ? v1 * DSC : 0.0f);
                    }
                }
            }
        }
        __syncthreads();   // h1 (dropped) complete before cross-warp out-proj
        if (tid < NB * 2) {
            int b = tid >> 1, o = tid & 1;
            const float* wr = F + F_WOUT + o * HH;
            float s = F[F_BOUT + o];
#pragma unroll
            for (int kk = 0; kk < 64; ++kk) {
                uint32_t off = abyte((uint32_t)b, (uint32_t)(2 * kk));
                __nv_bfloat162 hp = *(const __nv_bfloat162*)(smc + A_H1H + off);
                __nv_bfloat162 lp = *(const __nv_bfloat162*)(smc + A_H1L + off);
                float2 w = *(const float2*)(wr + 2 * kk);
                s += (__bfloat162float(hp.x) + __bfloat162float(lp.x)) * w.x
                   + (__bfloat162float(hp.y) + __bfloat162float(lp.y)) * w.y;
            }
            out[((size_t)(bbase + b) * PLL + p) * OO + o] = s;
            F[F_INP + b * 2 + o] = s;
        }
        __syncthreads();
    }
}

extern "C" void kernel_launch(void* const* d_in, const int* in_sizes, int n_in,
                              void* d_out, int out_size)
{
    (void)in_sizes; (void)n_in; (void)out_size;
    const float* obs   = (const float*)d_in[0];
    const float* Wih0  = (const float*)d_in[1];
    const float* Whh0  = (const float*)d_in[2];
    const float* bih0  = (const float*)d_in[3];
    const float* bhh0  = (const float*)d_in[4];
    const float* Wih1  = (const float*)d_in[5];
    const float* Whh1  = (const float*)d_in[6];
    const float* bih1  = (const float*)d_in[7];
    const float* bhh1  = (const float*)d_in[8];
    const float* Wihc  = (const float*)d_in[9];
    const float* Whhc  = (const float*)d_in[10];
    const float* bihc  = (const float*)d_in[11];
    const float* bhhc  = (const float*)d_in[12];
    const float* Wout  = (const float*)d_in[13];
    const float* bout  = (const float*)d_in[14];
    const float* enc_u = (const float*)d_in[15];
    const float* hn_u  = (const float*)d_in[16];
    const float* dec_u = (const float*)d_in[17];
    float* out = (float*)d_out;

    prep_kernel<<<GG * HH / 256, 256>>>(Whh0, Wih1, Whh1, Whhc);

    cudaFuncSetAttribute(mcdlstm_kernel,
                         cudaFuncAttributeMaxDynamicSharedMemorySize, SMEM_BYTES);
    mcdlstm_kernel<<<BTOT / NB, NTH, SMEM_BYTES>>>(
        obs, Wih0, bih0, bhh0, bih1, bhh1,
        Wihc, bihc, bhhc, Wout, bout, enc_u, hn_u, dec_u, out);
}